// round 7
// baseline (speedup 1.0000x reference)
#include <cuda_runtime.h>
#include <cuda_bf16.h>
#include <mma.h>
#include <math.h>
#include <stdint.h>

using namespace nvcuda;

// Problem constants: N=100000, F=256, UNITS=256, DIM=128
#define F_DIM   256
#define UNITS   256
#define DIM     128
#define N_MAX   100000
#define M_TILE  128
#define THREADS 512
#define LDA     264          // padded A smem leading dim (elements)
#define LDB     40           // padded B smem leading dim (elements)
#define KC      32           // K chunk per pipeline stage

// Scratch
__device__ float         g_x[(size_t)N_MAX * UNITS];   // ~102.4 MB
__device__ int           g_rowptr[N_MAX + 1];
__device__ float         g_kl;
__device__ __nv_bfloat16 g_Wh[UNITS * F_DIM];          // W^T hi, [n][k]
__device__ __nv_bfloat16 g_Wl[UNITS * F_DIM];          // W^T lo, [n][k]

// ---------------------------------------------------------------------------
// MUFU-free exp (x <= 0) and elu
// ---------------------------------------------------------------------------
__device__ __forceinline__ float fast_exp(float x) {
    x = fmaxf(x, -80.f);
    const float t = x * 1.4426950408889634f;
    const float nf = rintf(t);
    const float f = t - nf;
    float p = 1.5253232e-5f;
    p = fmaf(p, f, 1.54035304e-4f);
    p = fmaf(p, f, 1.33335581e-3f);
    p = fmaf(p, f, 9.61812911e-3f);
    p = fmaf(p, f, 5.55041087e-2f);
    p = fmaf(p, f, 2.40226507e-1f);
    p = fmaf(p, f, 6.93147181e-1f);
    p = fmaf(p, f, 1.0f);
    return __int_as_float(__float_as_int(p) + (((int)nf) << 23));
}
__device__ __forceinline__ float elu_f(float x) {
    if (x > 0.f) return x;
    if (x > -0.5f) {
        float p = 1.98412698e-4f;
        p = fmaf(p, x, 1.38888889e-3f);
        p = fmaf(p, x, 8.33333333e-3f);
        p = fmaf(p, x, 4.16666667e-2f);
        p = fmaf(p, x, 1.66666667e-1f);
        p = fmaf(p, x, 0.5f);
        p = fmaf(p, x, 1.0f);
        return x * p;
    }
    return fast_exp(x) - 1.0f;
}

__device__ __forceinline__ uint32_t smem_u32(const void* p) {
    uint32_t a;
    asm("{ .reg .u64 t; cvta.to.shared.u64 t, %1; cvt.u32.u64 %0, t; }"
        : "=r"(a) : "l"(p));
    return a;
}
__device__ __forceinline__ void cp_async16(uint32_t dst, const void* src) {
    asm volatile("cp.async.cg.shared.global [%0], [%1], 16;"
                 :: "r"(dst), "l"(src) : "memory");
}
#define CP_COMMIT() asm volatile("cp.async.commit_group;" ::: "memory")
#define CP_WAIT0()  asm volatile("cp.async.wait_group 0;" ::: "memory")

// ---------------------------------------------------------------------------
// Kernel 1: CSR row_ptr via boundary scatter
// ---------------------------------------------------------------------------
__global__ void build_rowptr_kernel(const int* __restrict__ row, int n, int e) {
    int i = blockIdx.x * blockDim.x + threadIdx.x;
    if (i == 0) g_kl = 0.0f;
    if (i > e) return;
    int prev = (i == 0) ? -1 : row[i - 1];
    int cur  = (i == e) ? n  : row[i];
    for (int j = prev + 1; j <= cur; j++) g_rowptr[j] = i;
}

// ---------------------------------------------------------------------------
// Kernel 1b: split W (fp32 [K,N]) into transposed bf16 hi/lo [N,K]
// ---------------------------------------------------------------------------
__global__ void wsplit_kernel(const float* __restrict__ W) {
    int i = blockIdx.x * blockDim.x + threadIdx.x;
    if (i >= UNITS * F_DIM) return;
    const int nn = i / F_DIM, kk = i % F_DIM;
    const float w = W[kk * UNITS + nn];
    const __nv_bfloat16 h = __float2bfloat16(w);
    g_Wh[i] = h;
    g_Wl[i] = __float2bfloat16(w - __bfloat162float(h));
}

// ---------------------------------------------------------------------------
// Kernel 2: WMMA bf16x3 GEMM, cp.async double-buffered B, 512 thr / 1 CTA/SM.
// M_TILE=128 rows; 16 warps; warp (rg=wid>>2, cg=wid&3) owns 32 rows x 64 cols.
// SMEM: Ah/Al [128][264] (132KB), B 2 buffers x (Bh+Bl [256][40]) (80KB).
// ---------------------------------------------------------------------------
__global__ __launch_bounds__(THREADS) void gemm_wmma_kernel(
    const float* __restrict__ feat, int n)
{
    extern __shared__ char smem[];
    __nv_bfloat16* Ah = reinterpret_cast<__nv_bfloat16*>(smem);
    __nv_bfloat16* Al = Ah + M_TILE * LDA;
    __nv_bfloat16* Bbase = Al + M_TILE * LDA;        // 2 bufs x 2*256*LDB elems
    float* C = reinterpret_cast<float*>(smem);       // reuse A region (131KB)

    const int tid = threadIdx.x;
    const int wid = tid >> 5, lane = tid & 31;
    const int row0 = blockIdx.x * M_TILE;
    const int nrows = min(M_TILE, n - row0);

    const int BUF_ELEMS = 2 * 256 * LDB;             // hi+lo per buffer

    // issue cp.async for chunk 0 immediately (overlaps with A staging)
    {
        const int b = 0, kc = 0;
        __nv_bfloat16* Bh = Bbase + b * BUF_ELEMS;
        __nv_bfloat16* Bl = Bh + 256 * LDB;
#pragma unroll
        for (int it = 0; it < 2; it++) {
            const int g = it * THREADS + tid;        // 0..1023
            const int nn = g >> 2;
            const int k8 = (g & 3) << 3;
            const size_t goff = (size_t)nn * F_DIM + kc + k8;
            cp_async16(smem_u32(Bh + nn * LDB + k8), g_Wh + goff);
            cp_async16(smem_u32(Bl + nn * LDB + k8), g_Wl + goff);
        }
        CP_COMMIT();
    }

    // --- stage A: fp32 -> bf16 hi/lo, padded rows ---
#pragma unroll
    for (int it = 0; it < 16; it++) {
        const int j = it * THREADS + tid;            // float4 id, 0..8191
        const int r = j >> 6;                        // row 0..127
        const int c4 = (j & 63) << 2;
        float4 v = make_float4(0.f, 0.f, 0.f, 0.f);
        if (r < nrows)
            v = reinterpret_cast<const float4*>(feat + (size_t)(row0 + r) * F_DIM)[j & 63];
        const __nv_bfloat16 h0 = __float2bfloat16(v.x);
        const __nv_bfloat16 h1 = __float2bfloat16(v.y);
        const __nv_bfloat16 h2 = __float2bfloat16(v.z);
        const __nv_bfloat16 h3 = __float2bfloat16(v.w);
        __nv_bfloat162 ph0; ph0.x = h0; ph0.y = h1;
        __nv_bfloat162 ph1; ph1.x = h2; ph1.y = h3;
        __nv_bfloat162 pl0, pl1;
        pl0.x = __float2bfloat16(v.x - __bfloat162float(h0));
        pl0.y = __float2bfloat16(v.y - __bfloat162float(h1));
        pl1.x = __float2bfloat16(v.z - __bfloat162float(h2));
        pl1.y = __float2bfloat16(v.w - __bfloat162float(h3));
        reinterpret_cast<__nv_bfloat162*>(Ah + r * LDA + c4)[0] = ph0;
        reinterpret_cast<__nv_bfloat162*>(Ah + r * LDA + c4)[1] = ph1;
        reinterpret_cast<__nv_bfloat162*>(Al + r * LDA + c4)[0] = pl0;
        reinterpret_cast<__nv_bfloat162*>(Al + r * LDA + c4)[1] = pl1;
    }

    const int rg = wid >> 2;            // 0..3  (row group, 32 rows)
    const int cg = wid & 3;             // 0..3  (col group, 64 cols)

    wmma::fragment<wmma::accumulator, 16, 16, 16, float> acc[2][4];
#pragma unroll
    for (int i = 0; i < 2; i++)
#pragma unroll
        for (int j = 0; j < 4; j++) wmma::fill_fragment(acc[i][j], 0.0f);

    CP_WAIT0();
    __syncthreads();     // A staged + B chunk 0 visible

    // --- pipelined mainloop over 8 K-chunks of 32 ---
    for (int c = 0; c < 8; c++) {
        const int kc = c * KC;
        // issue prefetch of chunk c+1 into the other buffer (all warps past
        // the barrier => nobody is still reading that buffer)
        if (c < 7) {
            const int b = (c + 1) & 1;
            const int kcn = kc + KC;
            __nv_bfloat16* Bh = Bbase + b * BUF_ELEMS;
            __nv_bfloat16* Bl = Bh + 256 * LDB;
#pragma unroll
            for (int it = 0; it < 2; it++) {
                const int g = it * THREADS + tid;
                const int nn = g >> 2;
                const int k8 = (g & 3) << 3;
                const size_t goff = (size_t)nn * F_DIM + kcn + k8;
                cp_async16(smem_u32(Bh + nn * LDB + k8), g_Wh + goff);
                cp_async16(smem_u32(Bl + nn * LDB + k8), g_Wl + goff);
            }
            CP_COMMIT();
        }

        // MMAs on buffer c&1 (loads of chunk c+1 fly underneath)
        const __nv_bfloat16* Bh = Bbase + (c & 1) * BUF_ELEMS;
        const __nv_bfloat16* Bl = Bh + 256 * LDB;
#pragma unroll
        for (int ks = 0; ks < KC; ks += 16) {
            wmma::fragment<wmma::matrix_a, 16, 16, 16, __nv_bfloat16, wmma::row_major> fah[2], fal[2];
#pragma unroll
            for (int i = 0; i < 2; i++) {
                const int r = rg * 32 + i * 16;
                wmma::load_matrix_sync(fah[i], Ah + r * LDA + kc + ks, LDA);
                wmma::load_matrix_sync(fal[i], Al + r * LDA + kc + ks, LDA);
            }
#pragma unroll
            for (int j = 0; j < 4; j++) {
                const int ncol = cg * 64 + j * 16;
                wmma::fragment<wmma::matrix_b, 16, 16, 16, __nv_bfloat16, wmma::col_major> fbh, fbl;
                wmma::load_matrix_sync(fbh, Bh + ncol * LDB + ks, LDB);
                wmma::load_matrix_sync(fbl, Bl + ncol * LDB + ks, LDB);
                // pass-major: same-acc updates spaced by independent MMAs
                wmma::mma_sync(acc[0][j], fah[0], fbh, acc[0][j]);
                wmma::mma_sync(acc[1][j], fah[1], fbh, acc[1][j]);
                wmma::mma_sync(acc[0][j], fah[0], fbl, acc[0][j]);
                wmma::mma_sync(acc[1][j], fah[1], fbl, acc[1][j]);
                wmma::mma_sync(acc[0][j], fal[0], fbh, acc[0][j]);
                wmma::mma_sync(acc[1][j], fal[1], fbh, acc[1][j]);
            }
        }

        if (c < 7) {
            CP_WAIT0();       // chunk c+1 landed (flew during the MMAs)
            __syncthreads();  // all warps done reading buffer c&1
        }
    }
    __syncthreads();   // A smem no longer needed; reuse as C

#pragma unroll
    for (int i = 0; i < 2; i++)
#pragma unroll
        for (int j = 0; j < 4; j++)
            wmma::store_matrix_sync(C + (rg * 32 + i * 16) * UNITS + cg * 64 + j * 16,
                                    acc[i][j], UNITS, wmma::mem_row_major);
    __syncthreads();

    // --- epilogue: activations, attention, KL, g_x ---
    float kl = 0.f;
#pragma unroll
    for (int it = 0; it < 32; it++) {
        const int idx = it * THREADS + tid;          // 0..16383
        const int r = idx >> 7;                      // 0..127
        const int d = idx & 127;
        if (r < nrows) {
            const float hm = C[r * UNITS + d];
            const float hv = C[r * UNITS + DIM + d];
            const float m = elu_f(hm);
            const float v = hv > 0.f ? hv : 0.f;
            const float att = fast_exp(-v);
            kl += m * m + v - logf(1e-8f + v) - 1.f;
            const size_t base = (size_t)(row0 + r) * UNITS;
            g_x[base + d]       = m * att;
            g_x[base + DIM + d] = v * att * att;
        }
    }
    kl *= 0.5f / (float)DIM;

    __shared__ float kl_red[16];
#pragma unroll
    for (int off = 16; off > 0; off >>= 1)
        kl += __shfl_down_sync(0xFFFFFFFFu, kl, off);
    if (lane == 0) kl_red[wid] = kl;
    __syncthreads();
    if (tid == 0) {
        float s = 0.f;
#pragma unroll
        for (int i = 0; i < 16; i++) s += kl_red[i];
        atomicAdd(&g_kl, s);
    }
}

// ---------------------------------------------------------------------------
// Kernel 3: fused dual SpMM, 2 warps per node, 8-way unrolled gathers
// (R5 version — the streaming hints of R6 regressed; reverted)
// ---------------------------------------------------------------------------
__global__ void spmm_kernel(
    const int* __restrict__ col,
    const float* __restrict__ a1,
    const float* __restrict__ a2,
    float* __restrict__ out,
    int n, int write_kl)
{
    const int gtid = blockIdx.x * blockDim.x + threadIdx.x;
    if (gtid == 0 && write_kl) out[(size_t)n * UNITS] = g_kl;

    const int work = gtid >> 5;
    const int node = work >> 1;
    const int half = work & 1;
    const int lane = threadIdx.x & 31;
    if (node >= n) return;

    const int s = g_rowptr[node];
    const int e = g_rowptr[node + 1];
    const float* __restrict__ av = half ? a2 : a1;
    const float* __restrict__ xb = g_x + half * DIM;

    float4 acc = make_float4(0.f, 0.f, 0.f, 0.f);
    int i = s;
    for (; i + 7 < e; i += 8) {
        int   c[8];
        float w[8];
#pragma unroll
        for (int u = 0; u < 8; u++) { c[u] = __ldg(&col[i + u]); w[u] = __ldg(&av[i + u]); }
        float4 x[8];
#pragma unroll
        for (int u = 0; u < 8; u++)
            x[u] = __ldg(&reinterpret_cast<const float4*>(xb + (size_t)c[u] * UNITS)[lane]);
#pragma unroll
        for (int u = 0; u < 8; u++) {
            acc.x = fmaf(w[u], x[u].x, acc.x); acc.y = fmaf(w[u], x[u].y, acc.y);
            acc.z = fmaf(w[u], x[u].z, acc.z); acc.w = fmaf(w[u], x[u].w, acc.w);
        }
    }
    for (; i < e; i++) {
        const int c0 = __ldg(&col[i]);
        const float w0 = __ldg(&av[i]);
        const float4 x0 = __ldg(&reinterpret_cast<const float4*>(xb + (size_t)c0 * UNITS)[lane]);
        acc.x = fmaf(w0, x0.x, acc.x); acc.y = fmaf(w0, x0.y, acc.y);
        acc.z = fmaf(w0, x0.z, acc.z); acc.w = fmaf(w0, x0.w, acc.w);
    }
    reinterpret_cast<float4*>(out + (size_t)node * UNITS + half * DIM)[lane] = acc;
}

// ---------------------------------------------------------------------------
extern "C" void kernel_launch(void* const* d_in, const int* in_sizes, int n_in,
                              void* d_out, int out_size) {
    const float* feat = (const float*)d_in[0];
    const float* W    = (const float*)d_in[1];
    const int*   row  = (const int*)d_in[2];
    const int*   col  = (const int*)d_in[3];
    const float* a1   = (const float*)d_in[4];
    const float* a2   = (const float*)d_in[5];
    float* out = (float*)d_out;

    const int n = in_sizes[0] / F_DIM;
    const int e = in_sizes[2];
    const int write_kl = (out_size > n * UNITS) ? 1 : 0;

    {   // CSR row pointers
        const int threads = 256;
        build_rowptr_kernel<<<(e + 1 + threads - 1) / threads, threads>>>(row, n, e);
    }
    {   // W split to bf16 hi/lo, transposed
        const int threads = 256;
        wsplit_kernel<<<(UNITS * F_DIM + threads - 1) / threads, threads>>>(W);
    }
    {   // WMMA GEMM + epilogue (212KB smem, 1 CTA/SM, cp.async pipeline)
        const int smem_total = 2 * M_TILE * LDA * 2 + 2 * (2 * 256 * LDB) * 2; // 217088
        cudaFuncSetAttribute(gemm_wmma_kernel,
                             cudaFuncAttributeMaxDynamicSharedMemorySize, smem_total);
        gemm_wmma_kernel<<<(n + M_TILE - 1) / M_TILE, THREADS, smem_total>>>(feat, n);
    }
    {   // dual SpMM
        const int threads = 256;
        const int warps_needed = 2 * n;
        spmm_kernel<<<(warps_needed + 7) / 8, threads>>>(col, a1, a2, out, n, write_kl);
    }
}

// round 8
// speedup vs baseline: 1.5175x; 1.5175x over previous
#include <cuda_runtime.h>
#include <cuda_fp16.h>
#include <mma.h>
#include <math.h>
#include <stdint.h>

using namespace nvcuda;

// Problem constants: N=100000, F=256, UNITS=256, DIM=128
#define F_DIM   256
#define UNITS   256
#define DIM     128
#define N_MAX   100000
#define M_TILE  64
#define THREADS 256
#define LDA     264          // A smem leading dim (halfs), 528B stride
#define LDB     24           // B smem leading dim (halfs), 48B stride
#define LDC     260          // C smem leading dim (floats), 1040B stride
#define KC      16           // K chunk per pipeline stage
#define NCHUNK  (F_DIM / KC) // 16

// Scratch
__device__ __half g_xh[(size_t)N_MAX * UNITS];   // packed [mean|var] fp16, ~51 MB
__device__ int    g_rowptr[N_MAX + 1];
__device__ float  g_kl;
__device__ __half g_Wh[UNITS * F_DIM];           // W^T hi fp16, [n][k]
__device__ __half g_Wl[UNITS * F_DIM];           // W^T lo fp16, [n][k]

// ---------------------------------------------------------------------------
// MUFU-free exp (x <= 0) and elu
// ---------------------------------------------------------------------------
__device__ __forceinline__ float fast_exp(float x) {
    x = fmaxf(x, -80.f);
    const float t = x * 1.4426950408889634f;
    const float nf = rintf(t);
    const float f = t - nf;
    float p = 1.5253232e-5f;
    p = fmaf(p, f, 1.54035304e-4f);
    p = fmaf(p, f, 1.33335581e-3f);
    p = fmaf(p, f, 9.61812911e-3f);
    p = fmaf(p, f, 5.55041087e-2f);
    p = fmaf(p, f, 2.40226507e-1f);
    p = fmaf(p, f, 6.93147181e-1f);
    p = fmaf(p, f, 1.0f);
    return __int_as_float(__float_as_int(p) + (((int)nf) << 23));
}
__device__ __forceinline__ float elu_f(float x) {
    if (x > 0.f) return x;
    if (x > -0.5f) {
        float p = 1.98412698e-4f;
        p = fmaf(p, x, 1.38888889e-3f);
        p = fmaf(p, x, 8.33333333e-3f);
        p = fmaf(p, x, 4.16666667e-2f);
        p = fmaf(p, x, 1.66666667e-1f);
        p = fmaf(p, x, 0.5f);
        p = fmaf(p, x, 1.0f);
        return x * p;
    }
    return fast_exp(x) - 1.0f;
}

__device__ __forceinline__ uint32_t smem_u32(const void* p) {
    uint32_t a;
    asm("{ .reg .u64 t; cvta.to.shared.u64 t, %1; cvt.u32.u64 %0, t; }"
        : "=r"(a) : "l"(p));
    return a;
}
__device__ __forceinline__ void cp_async16(uint32_t dst, const void* src) {
    asm volatile("cp.async.cg.shared.global [%0], [%1], 16;"
                 :: "r"(dst), "l"(src) : "memory");
}
#define CP_COMMIT() asm volatile("cp.async.commit_group;" ::: "memory")
#define CP_WAIT0()  asm volatile("cp.async.wait_group 0;" ::: "memory")

// ---------------------------------------------------------------------------
// Kernel 1: CSR row_ptr via boundary scatter
// ---------------------------------------------------------------------------
__global__ void build_rowptr_kernel(const int* __restrict__ row, int n, int e) {
    int i = blockIdx.x * blockDim.x + threadIdx.x;
    if (i == 0) g_kl = 0.0f;
    if (i > e) return;
    int prev = (i == 0) ? -1 : row[i - 1];
    int cur  = (i == e) ? n  : row[i];
    for (int j = prev + 1; j <= cur; j++) g_rowptr[j] = i;
}

// ---------------------------------------------------------------------------
// Kernel 1b: split W (fp32 [K,N]) into transposed fp16 hi/lo [N,K]
// ---------------------------------------------------------------------------
__global__ void wsplit_kernel(const float* __restrict__ W) {
    int i = blockIdx.x * blockDim.x + threadIdx.x;
    if (i >= UNITS * F_DIM) return;
    const int nn = i / F_DIM, kk = i % F_DIM;
    const float w = W[kk * UNITS + nn];
    const __half h = __float2half(w);
    g_Wh[i] = h;
    g_Wl[i] = __float2half(w - __half2float(h));
}

// ---------------------------------------------------------------------------
// Kernel 2: WMMA fp16 2-pass GEMM (D = Ah*Wh + Ah*Wl), cp.async pipelined.
// 256 thr (8 warps), M_TILE=64, 2 CTAs/SM (83KB smem each).
// Warp (rg=wid>>2, cg=wid&3) owns 32 rows x 64 cols.
// ---------------------------------------------------------------------------
__global__ __launch_bounds__(THREADS, 2) void gemm_wmma_kernel(
    const float* __restrict__ feat, int n)
{
    extern __shared__ char smem[];
    __half* Ah = reinterpret_cast<__half*>(smem);        // 64*264*2 = 33792 B
    __half* Bbase = Ah + M_TILE * LDA;                   // 2 bufs x 12288 halfs
    float* C = reinterpret_cast<float*>(smem);           // epilogue reuse (66.6KB)

    const int tid = threadIdx.x;
    const int wid = tid >> 5, lane = tid & 31;
    const int row0 = blockIdx.x * M_TILE;
    const int nrows = min(M_TILE, n - row0);

    const int BUF_ELEMS = 2 * 256 * LDB;                 // hi+lo per buffer

    // prefetch B chunk 0 (overlaps with A staging)
    {
        __half* Bh = Bbase;
        __half* Bl = Bh + 256 * LDB;
#pragma unroll
        for (int it = 0; it < 2; it++) {
            const int g = it * THREADS + tid;            // 0..511
            const int nn = g >> 1;                       // 0..255
            const int k8 = (g & 1) << 3;                 // 0 or 8
            cp_async16(smem_u32(Bh + nn * LDB + k8), g_Wh + (size_t)nn * F_DIM + k8);
            cp_async16(smem_u32(Bl + nn * LDB + k8), g_Wl + (size_t)nn * F_DIM + k8);
        }
        CP_COMMIT();
    }

    // --- stage A: fp32 -> fp16 (single split) ---
#pragma unroll
    for (int it = 0; it < 16; it++) {
        const int j = it * THREADS + tid;                // float4 id, 0..4095
        const int r = j >> 6;                            // row 0..63
        const int c4 = (j & 63) << 2;
        float4 v = make_float4(0.f, 0.f, 0.f, 0.f);
        if (r < nrows)
            v = reinterpret_cast<const float4*>(feat + (size_t)(row0 + r) * F_DIM)[j & 63];
        __half2 p0; p0.x = __float2half(v.x); p0.y = __float2half(v.y);
        __half2 p1; p1.x = __float2half(v.z); p1.y = __float2half(v.w);
        reinterpret_cast<__half2*>(Ah + r * LDA + c4)[0] = p0;
        reinterpret_cast<__half2*>(Ah + r * LDA + c4)[1] = p1;
    }

    const int rg = wid >> 2;            // 0..1 (32-row group)
    const int cg = wid & 3;             // 0..3 (64-col group)

    wmma::fragment<wmma::accumulator, 16, 16, 16, float> acc[2][4];
#pragma unroll
    for (int i = 0; i < 2; i++)
#pragma unroll
        for (int j = 0; j < 4; j++) wmma::fill_fragment(acc[i][j], 0.0f);

    CP_WAIT0();
    __syncthreads();

    // --- pipelined mainloop over 16 K-chunks of 16 ---
    for (int c = 0; c < NCHUNK; c++) {
        const int kc = c * KC;
        if (c < NCHUNK - 1) {            // prefetch chunk c+1
            const int b = (c + 1) & 1;
            const int kcn = kc + KC;
            __half* Bh = Bbase + b * BUF_ELEMS;
            __half* Bl = Bh + 256 * LDB;
#pragma unroll
            for (int it = 0; it < 2; it++) {
                const int g = it * THREADS + tid;
                const int nn = g >> 1;
                const int k8 = (g & 1) << 3;
                const size_t goff = (size_t)nn * F_DIM + kcn + k8;
                cp_async16(smem_u32(Bh + nn * LDB + k8), g_Wh + goff);
                cp_async16(smem_u32(Bl + nn * LDB + k8), g_Wl + goff);
            }
            CP_COMMIT();
        }

        const __half* Bh = Bbase + (c & 1) * BUF_ELEMS;
        const __half* Bl = Bh + 256 * LDB;

        wmma::fragment<wmma::matrix_a, 16, 16, 16, __half, wmma::row_major> fah[2];
#pragma unroll
        for (int i = 0; i < 2; i++)
            wmma::load_matrix_sync(fah[i], Ah + (rg * 32 + i * 16) * LDA + kc, LDA);
#pragma unroll
        for (int j = 0; j < 4; j++) {
            const int ncol = cg * 64 + j * 16;
            wmma::fragment<wmma::matrix_b, 16, 16, 16, __half, wmma::col_major> fbh, fbl;
            wmma::load_matrix_sync(fbh, Bh + ncol * LDB, LDB);
            wmma::load_matrix_sync(fbl, Bl + ncol * LDB, LDB);
            wmma::mma_sync(acc[0][j], fah[0], fbh, acc[0][j]);
            wmma::mma_sync(acc[1][j], fah[1], fbh, acc[1][j]);
            wmma::mma_sync(acc[0][j], fah[0], fbl, acc[0][j]);
            wmma::mma_sync(acc[1][j], fah[1], fbl, acc[1][j]);
        }

        if (c < NCHUNK - 1) {
            CP_WAIT0();
            __syncthreads();
        }
    }
    __syncthreads();   // smem no longer needed as A/B; reuse as C

#pragma unroll
    for (int i = 0; i < 2; i++)
#pragma unroll
        for (int j = 0; j < 4; j++)
            wmma::store_matrix_sync(C + (rg * 32 + i * 16) * LDC + cg * 64 + j * 16,
                                    acc[i][j], LDC, wmma::mem_row_major);
    __syncthreads();

    // --- epilogue: activations, attention, KL; g_x in fp16 ---
    float kl = 0.f;
#pragma unroll
    for (int it = 0; it < 16; it++) {
        const int idx = it * THREADS + tid;              // 0..4095
        const int r = idx >> 6;                          // 0..63
        const int d2 = (idx & 63) << 1;                  // even d, 0..126
        if (r < nrows) {
            float mo[2], vo[2];
#pragma unroll
            for (int q = 0; q < 2; q++) {
                const float hm = C[r * LDC + d2 + q];
                const float hv = C[r * LDC + DIM + d2 + q];
                const float m = elu_f(hm);
                const float v = hv > 0.f ? hv : 0.f;
                const float att = fast_exp(-v);
                kl += m * m + v - logf(1e-8f + v) - 1.f;
                mo[q] = m * att;
                vo[q] = v * att * att;
            }
            const size_t base = (size_t)(row0 + r) * UNITS;
            __half2 hm2; hm2.x = __float2half(mo[0]); hm2.y = __float2half(mo[1]);
            __half2 hv2; hv2.x = __float2half(vo[0]); hv2.y = __float2half(vo[1]);
            *reinterpret_cast<__half2*>(g_xh + base + d2)       = hm2;
            *reinterpret_cast<__half2*>(g_xh + base + DIM + d2) = hv2;
        }
    }
    kl *= 0.5f / (float)DIM;

    __shared__ float kl_red[8];
#pragma unroll
    for (int off = 16; off > 0; off >>= 1)
        kl += __shfl_down_sync(0xFFFFFFFFu, kl, off);
    if (lane == 0) kl_red[wid] = kl;
    __syncthreads();
    if (tid == 0) {
        float s = 0.f;
#pragma unroll
        for (int i = 0; i < 8; i++) s += kl_red[i];
        atomicAdd(&g_kl, s);
    }
}

// ---------------------------------------------------------------------------
// Kernel 3: fused dual SpMM on fp16 table. ONE warp per node covers the full
// 512B row: lanes 0-15 = mean half (adj1), lanes 16-31 = var half (adj2).
// ---------------------------------------------------------------------------
__global__ void spmm_kernel(
    const int* __restrict__ col,
    const float* __restrict__ a1,
    const float* __restrict__ a2,
    float* __restrict__ out,
    int n, int write_kl)
{
    const int gtid = blockIdx.x * blockDim.x + threadIdx.x;
    if (gtid == 0 && write_kl) out[(size_t)n * UNITS] = g_kl;

    const int node = gtid >> 5;
    const int lane = threadIdx.x & 31;
    if (node >= n) return;

    const int s = g_rowptr[node];
    const int e = g_rowptr[node + 1];
    const float* __restrict__ wa = (lane < 16) ? a1 : a2;

    float acc[8];
#pragma unroll
    for (int q = 0; q < 8; q++) acc[q] = 0.f;

    int i = s;
    for (; i + 3 < e; i += 4) {
        int   c[4];
        float w[4];
        uint4 x[4];
#pragma unroll
        for (int u = 0; u < 4; u++) { c[u] = __ldg(&col[i + u]); w[u] = __ldg(&wa[i + u]); }
#pragma unroll
        for (int u = 0; u < 4; u++)
            x[u] = __ldg(reinterpret_cast<const uint4*>(g_xh + (size_t)c[u] * UNITS) + lane);
#pragma unroll
        for (int u = 0; u < 4; u++) {
            const __half2* hp = reinterpret_cast<const __half2*>(&x[u]);
#pragma unroll
            for (int q = 0; q < 4; q++) {
                const float2 f = __half22float2(hp[q]);
                acc[2 * q]     = fmaf(w[u], f.x, acc[2 * q]);
                acc[2 * q + 1] = fmaf(w[u], f.y, acc[2 * q + 1]);
            }
        }
    }
    for (; i < e; i++) {
        const int c0 = __ldg(&col[i]);
        const float w0 = __ldg(&wa[i]);
        const uint4 x0 = __ldg(reinterpret_cast<const uint4*>(g_xh + (size_t)c0 * UNITS) + lane);
        const __half2* hp = reinterpret_cast<const __half2*>(&x0);
#pragma unroll
        for (int q = 0; q < 4; q++) {
            const float2 f = __half22float2(hp[q]);
            acc[2 * q]     = fmaf(w0, f.x, acc[2 * q]);
            acc[2 * q + 1] = fmaf(w0, f.y, acc[2 * q + 1]);
        }
    }

    float* o = out + (size_t)node * UNITS + lane * 8;
    *reinterpret_cast<float4*>(o)     = make_float4(acc[0], acc[1], acc[2], acc[3]);
    *reinterpret_cast<float4*>(o + 4) = make_float4(acc[4], acc[5], acc[6], acc[7]);
}

// ---------------------------------------------------------------------------
extern "C" void kernel_launch(void* const* d_in, const int* in_sizes, int n_in,
                              void* d_out, int out_size) {
    const float* feat = (const float*)d_in[0];
    const float* W    = (const float*)d_in[1];
    const int*   row  = (const int*)d_in[2];
    const int*   col  = (const int*)d_in[3];
    const float* a1   = (const float*)d_in[4];
    const float* a2   = (const float*)d_in[5];
    float* out = (float*)d_out;

    const int n = in_sizes[0] / F_DIM;
    const int e = in_sizes[2];
    const int write_kl = (out_size > n * UNITS) ? 1 : 0;

    {   // CSR row pointers
        const int threads = 256;
        build_rowptr_kernel<<<(e + 1 + threads - 1) / threads, threads>>>(row, n, e);
    }
    {   // W split to fp16 hi/lo, transposed
        const int threads = 256;
        wsplit_kernel<<<(UNITS * F_DIM + threads - 1) / threads, threads>>>(W);
    }
    {   // fp16 2-pass WMMA GEMM + epilogue (83KB smem, 2 CTAs/SM)
        const int smem_total = M_TILE * LDA * 2 + 2 * (2 * 256 * LDB) * 2; // 82944
        cudaFuncSetAttribute(gemm_wmma_kernel,
                             cudaFuncAttributeMaxDynamicSharedMemorySize, smem_total);
        gemm_wmma_kernel<<<(n + M_TILE - 1) / M_TILE, THREADS, smem_total>>>(feat, n);
    }
    {   // dual SpMM, 1 warp per node
        const int threads = 256;
        spmm_kernel<<<(n * 32 + threads - 1) / threads, threads>>>(col, a1, a2, out, n, write_kl);
    }
}